// round 3
// baseline (speedup 1.0000x reference)
#include <cuda_runtime.h>
#include <math.h>

#define MAXNM1 511
#define MAXSP  (MAXNM1 + 2)
#define MAXSP2 (MAXSP * MAXSP)
#define MAXP   (MAXNM1 * MAXNM1)
#define MAXE   (2 * (MAXNM1 + 1) * MAXNM1)

// Messages as padded SoA planes: g_M[buf][slot][(pi+1)*sp + (pj+1)], pads = 1.0f
__device__ float4 g_M[2][4][MAXSP2];
__device__ float4 g_phiP[4][MAXP];
__device__ float4 g_phiE[MAXE];
__device__ double g_F;

// ---------------------------------------------------------------------------
__device__ __forceinline__ float fast_logf(float x) {
    int ix = __float_as_int(x);
    int ex = (ix >> 23) - 127;
    float m = __int_as_float((ix & 0x007FFFFF) | 0x3F800000);
    if (m > 1.41421356f) { m *= 0.5f; ex += 1; }
    float f = m - 1.0f;
    float z = f * f;
    float p = 7.0376836292e-2f;
    p = fmaf(p, f, -1.1514610310e-1f);
    p = fmaf(p, f,  1.1676998740e-1f);
    p = fmaf(p, f, -1.2420140846e-1f);
    p = fmaf(p, f,  1.4249322787e-1f);
    p = fmaf(p, f, -1.6668057665e-1f);
    p = fmaf(p, f,  2.0000714765e-1f);
    p = fmaf(p, f, -2.4999993993e-1f);
    p = fmaf(p, f,  3.3333331174e-1f);
    p = p * z * f;
    p = fmaf(-0.5f, z, p);
    return fmaf((float)ex, 0.693147180559945f, f + p);
}

__device__ __forceinline__ float pow2_inv_scale(float Z) {
    int eb = (__float_as_int(Z) >> 23) & 0xFF;
    return __int_as_float((254 - eb) << 23);
}

__device__ __forceinline__ void block_add_F(float v) {
    #pragma unroll
    for (int o = 16; o; o >>= 1) v += __shfl_down_sync(0xffffffffu, v, o);
    __shared__ float sh[32];
    int lane = threadIdx.x & 31, w = threadIdx.x >> 5;
    if (lane == 0) sh[w] = v;
    __syncthreads();
    if (w == 0) {
        int nw = (blockDim.x + 31) >> 5;
        float s = (lane < nw) ? sh[lane] : 0.0f;
        #pragma unroll
        for (int o = 16; o; o >>= 1) s += __shfl_down_sync(0xffffffffu, s, o);
        if (lane == 0) atomicAdd(&g_F, (double)s);
    }
}

__device__ __forceinline__ float4 exp4(float4 v) {
    return make_float4(__expf(v.x), __expf(v.y), __expf(v.z), __expf(v.w));
}

// ---------------------------------------------------------------------------
// Fused setup: y<4 -> phiP plane y;  y==4 -> phiE + pads + F=0
__global__ void k_setup(const float4* __restrict__ lpp,
                        const float4* __restrict__ lpe,
                        int P, int E, int sp) {
    int i = blockIdx.x * blockDim.x + threadIdx.x;
    int y = blockIdx.y;
    if (y < 4) {
        if (i < P) g_phiP[y][i] = exp4(__ldg(&lpp[i * 4 + y]));
    } else {
        if (i == 0) g_F = 0.0;
        if (i < E) g_phiE[i] = exp4(__ldg(&lpe[i]));
        if (i < sp) {
            float4 one = make_float4(1.f, 1.f, 1.f, 1.f);
            #pragma unroll
            for (int pl = 0; pl < 8; pl++) {
                float4* Mp = g_M[pl >> 2][pl & 3];
                Mp[i] = one;
                Mp[(sp - 1) * sp + i] = one;
                Mp[i * sp] = one;
                Mp[i * sp + (sp - 1)] = one;
            }
        }
    }
}

// ---------------------------------------------------------------------------
__device__ __forceinline__ float4 mul4(float4 a, float4 b) {
    return make_float4(a.x * b.x, a.y * b.y, a.z * b.z, a.w * b.w);
}

__device__ __forceinline__ void load_phi(int p, float Phi[16]) {
    float4 q;
    q = __ldg(&g_phiP[0][p]); Phi[0]  = q.x; Phi[1]  = q.y; Phi[2]  = q.z; Phi[3]  = q.w;
    q = __ldg(&g_phiP[1][p]); Phi[4]  = q.x; Phi[5]  = q.y; Phi[6]  = q.z; Phi[7]  = q.w;
    q = __ldg(&g_phiP[2][p]); Phi[8]  = q.x; Phi[9]  = q.y; Phi[10] = q.z; Phi[11] = q.w;
    q = __ldg(&g_phiP[3][p]); Phi[12] = q.x; Phi[13] = q.y; Phi[14] = q.z; Phi[15] = q.w;
}

// ---------------------------------------------------------------------------
template<bool FIRST>
__global__ void __launch_bounds__(128, 14) k_iter(int src, int nm1) {
    int pj = blockIdx.x * blockDim.x + threadIdx.x;
    int pi = blockIdx.y;
    if (pj >= nm1) return;
    int n = nm1 + 1, sp = nm1 + 2, nH = n * nm1;
    int p = pi * nm1 + pj;
    int q = (pi + 1) * sp + (pj + 1);

    float4 N0 = __ldg(&g_phiE[p]);
    float4 N1 = __ldg(&g_phiE[p + nm1]);
    int e2 = nH + pi * n + pj;
    float4 N2 = __ldg(&g_phiE[e2]);
    float4 N3 = __ldg(&g_phiE[e2 + 1]);
    if (!FIRST) {
        N0 = mul4(N0, __ldg(&g_M[src][1][q - sp]));
        N1 = mul4(N1, __ldg(&g_M[src][0][q + sp]));
        N2 = mul4(N2, __ldg(&g_M[src][3][q - 1]));
        N3 = mul4(N3, __ldg(&g_M[src][2][q + 1]));
    }
    float n0[4] = {N0.x, N0.y, N0.z, N0.w};
    float n1[4] = {N1.x, N1.y, N1.z, N1.w};
    float n2[4] = {N2.x, N2.y, N2.z, N2.w};
    float n3[4] = {N3.x, N3.y, N3.z, N3.w};
    float Phi[16];
    load_phi(p, Phi);

    float u0[4] = {0, 0, 0, 0}, u1[4] = {0, 0, 0, 0};
    float u2[4] = {0, 0, 0, 0}, u3[4] = {0, 0, 0, 0};
    #pragma unroll
    for (int a = 0; a < 2; a++)
    #pragma unroll
    for (int b = 0; b < 2; b++)
    #pragma unroll
    for (int c = 0; c < 2; c++)
    #pragma unroll
    for (int d = 0; d < 2; d++) {
        int idx = a * 8 + b * 4 + c * 2 + d;
        float ph = Phi[idx];
        float va = n0[a * 2 + b], vb = n1[c * 2 + d];
        float vc = n2[a * 2 + c], vd = n3[b * 2 + d];
        float q1 = ph * vc * vd;
        u0[a * 2 + b] = fmaf(q1, vb, u0[a * 2 + b]);
        u1[c * 2 + d] = fmaf(q1, va, u1[c * 2 + d]);
        float q2 = ph * va * vb;
        u2[a * 2 + c] = fmaf(q2, vd, u2[a * 2 + c]);
        u3[b * 2 + d] = fmaf(q2, vc, u3[b * 2 + d]);
    }

    int dst = src ^ 1;
    {
        float Z = (u0[0] + u0[1]) + (u0[2] + u0[3]); float s = pow2_inv_scale(Z);
        g_M[dst][0][q] = make_float4(u0[0] * s, u0[1] * s, u0[2] * s, u0[3] * s);
    }
    {
        float Z = (u1[0] + u1[1]) + (u1[2] + u1[3]); float s = pow2_inv_scale(Z);
        g_M[dst][1][q] = make_float4(u1[0] * s, u1[1] * s, u1[2] * s, u1[3] * s);
    }
    {
        float Z = (u2[0] + u2[1]) + (u2[2] + u2[3]); float s = pow2_inv_scale(Z);
        g_M[dst][2][q] = make_float4(u2[0] * s, u2[1] * s, u2[2] * s, u2[3] * s);
    }
    {
        float Z = (u3[0] + u3[1]) + (u3[2] + u3[3]); float s = pow2_inv_scale(Z);
        g_M[dst][3][q] = make_float4(u3[0] * s, u3[1] * s, u3[2] * s, u3[3] * s);
    }
}

// ---------------------------------------------------------------------------
// Fused finals: per (i,j) in [0,n)^2 compute h-edge(i,j), v-edge(i,j),
// plaquette F term(i,j). Shared message loads; one F reduction.
__global__ void k_final(int src, int nm1, const float4* __restrict__ lpe,
                        float* __restrict__ out) {
    int j = blockIdx.x * blockDim.x + threadIdx.x;
    int i = blockIdx.y;
    int n = nm1 + 1, sp = nm1 + 2, nH = n * nm1;
    float fterm = 0.0f;
    if (j < n) {
        int q = (i + 1) * sp + (j + 1);
        // shared message loads (pads give 1.0 on borders)
        float4 m_h0 = __ldg(&g_M[src][0][q]);        // h-edge parent below
        float4 m_h1 = __ldg(&g_M[src][1][q - sp]);   // h-edge parent above / plaq r0
        float4 m_v0 = __ldg(&g_M[src][2][q]);        // v-edge parent right
        float4 m_v1 = __ldg(&g_M[src][3][q - 1]);    // v-edge parent left / plaq r2
        int outB = 1 + 2 * n * n;

        // ---- horizontal edge e = i*nm1 + j (valid j < nm1) ----
        if (j < nm1) {
            int e = i * nm1 + j;
            float4 pe = __ldg(&g_phiE[e]);
            float tx = pe.x * m_h0.x * m_h1.x, ty = pe.y * m_h0.y * m_h1.y;
            float tz = pe.z * m_h0.z * m_h1.z, tw = pe.w * m_h0.w * m_h1.w;
            float Z = (tx + ty) + (tz + tw);
            float inv = __fdividef(1.0f, Z);
            float bx = tx * inv, by = ty * inv, bz = tz * inv, bw = tw * inv;
            int base = outB + e * 4;
            out[base + 0] = bx; out[base + 1] = by; out[base + 2] = bz; out[base + 3] = bw;
            if (i > 0 && i < nm1) {
                float4 lp = __ldg(&lpe[e]);
                fterm -= bx * (fast_logf(tx) - lp.x) + by * (fast_logf(ty) - lp.y)
                       + bz * (fast_logf(tz) - lp.z) + bw * (fast_logf(tw) - lp.w)
                       - fast_logf(Z);
            }
        }
        // ---- vertical edge e = nH + i*n + j (valid i < nm1) ----
        if (i < nm1) {
            int e = nH + i * n + j;
            float4 pe = __ldg(&g_phiE[e]);
            float tx = pe.x * m_v0.x * m_v1.x, ty = pe.y * m_v0.y * m_v1.y;
            float tz = pe.z * m_v0.z * m_v1.z, tw = pe.w * m_v0.w * m_v1.w;
            float Z = (tx + ty) + (tz + tw);
            float inv = __fdividef(1.0f, Z);
            float bx = tx * inv, by = ty * inv, bz = tz * inv, bw = tw * inv;
            int base = outB + e * 4;
            out[base + 0] = bx; out[base + 1] = by; out[base + 2] = bz; out[base + 3] = bw;
            if (j > 0 && j < nm1) {
                float4 lp = __ldg(&lpe[e]);
                fterm -= bx * (fast_logf(tx) - lp.x) + by * (fast_logf(ty) - lp.y)
                       + bz * (fast_logf(tz) - lp.z) + bw * (fast_logf(tw) - lp.w)
                       - fast_logf(Z);
            }
        }
        // ---- plaquette term (valid i < nm1 && j < nm1) ----
        if (i < nm1 && j < nm1) {
            int p = i * nm1 + j;
            float4 N0 = mul4(__ldg(&g_phiE[p]),        m_h1);                         // r0 = in1[q-sp]
            float4 N1 = mul4(__ldg(&g_phiE[p + nm1]),  __ldg(&g_M[src][0][q + sp]));
            int e2 = nH + i * n + j;
            float4 N2 = mul4(__ldg(&g_phiE[e2]),       m_v1);                         // r2 = in3[q-1]
            float4 N3 = mul4(__ldg(&g_phiE[e2 + 1]),   __ldg(&g_M[src][2][q + 1]));
            float n0[4] = {N0.x, N0.y, N0.z, N0.w};
            float n1[4] = {N1.x, N1.y, N1.z, N1.w};
            float n2[4] = {N2.x, N2.y, N2.z, N2.w};
            float n3[4] = {N3.x, N3.y, N3.z, N3.w};
            float Phi[16];
            load_phi(p, Phi);

            float t0[4] = {0, 0, 0, 0}, t1[4] = {0, 0, 0, 0};
            float t2[4] = {0, 0, 0, 0}, t3[4] = {0, 0, 0, 0};
            #pragma unroll
            for (int a = 0; a < 2; a++)
            #pragma unroll
            for (int b = 0; b < 2; b++)
            #pragma unroll
            for (int c = 0; c < 2; c++)
            #pragma unroll
            for (int d = 0; d < 2; d++) {
                int idx = a * 8 + b * 4 + c * 2 + d;
                float ev = Phi[idx] * n0[a * 2 + b] * n1[c * 2 + d]
                                    * n2[a * 2 + c] * n3[b * 2 + d];
                t0[a * 2 + b] += ev; t1[c * 2 + d] += ev;
                t2[a * 2 + c] += ev; t3[b * 2 + d] += ev;
            }
            float sumE = (t0[0] + t0[1]) + (t0[2] + t0[3]);
            float acc = 0.0f;
            #pragma unroll
            for (int x = 0; x < 4; x++) {
                acc = fmaf(t0[x], fast_logf(n0[x]), acc);
                acc = fmaf(t1[x], fast_logf(n1[x]), acc);
                acc = fmaf(t2[x], fast_logf(n2[x]), acc);
                acc = fmaf(t3[x], fast_logf(n3[x]), acc);
            }
            fterm += __fdividef(acc, sumE) - fast_logf(sumE);
        }
    }
    block_add_F(fterm);
}

// ---------------------------------------------------------------------------
__global__ void k_node(float* __restrict__ out, int n) {
    int j = blockIdx.x * blockDim.x + threadIdx.x;
    int i = blockIdx.y;
    if (j >= n) return;
    int nm1 = n - 1, nH = n * nm1;
    const float* B = out + 1 + 2 * n * n;
    float s0 = 0.f, s1 = 0.f; int deg = 0;
    if (j < nm1) { const float* b = B + (i * nm1 + j) * 4;          s0 += b[0] + b[1]; s1 += b[2] + b[3]; deg++; }
    if (j > 0)   { const float* b = B + (i * nm1 + j - 1) * 4;      s0 += b[0] + b[2]; s1 += b[1] + b[3]; deg++; }
    if (i < nm1) { const float* b = B + (nH + i * n + j) * 4;       s0 += b[0] + b[1]; s1 += b[2] + b[3]; deg++; }
    if (i > 0)   { const float* b = B + (nH + (i - 1) * n + j) * 4; s0 += b[0] + b[2]; s1 += b[1] + b[3]; deg++; }
    float invd = __fdividef(1.0f, (float)deg);
    int v = i * n + j;
    out[1 + v * 2 + 0] = s0 * invd;
    out[1 + v * 2 + 1] = s1 * invd;
}

__global__ void k_write_F(float* __restrict__ out) {
    if (threadIdx.x == 0 && blockIdx.x == 0) out[0] = (float)(-g_F);
}

// ---------------------------------------------------------------------------
extern "C" void kernel_launch(void* const* d_in, const int* in_sizes, int n_in,
                              void* d_out, int out_size) {
    const float* log_phi_plaq = (const float*)d_in[0];
    const float* log_phi_edge = (const float*)d_in[1];

    int P = in_sizes[0] / 16;
    int E = in_sizes[1] / 4;
    int nm1 = (int)lrint(sqrt((double)P));
    int n = nm1 + 1;
    int sp = nm1 + 2;
    (void)n_in; (void)out_size;
    float* out = (float*)d_out;

    const int NITERS = 5;

    k_setup<<<dim3((E + 255) / 256, 5), 256>>>(
        (const float4*)log_phi_plaq, (const float4*)log_phi_edge, P, E, sp);

    dim3 bs(128);
    dim3 gr((nm1 + 127) / 128, nm1);
    int src = 0;
    k_iter<true><<<gr, bs>>>(src, nm1);
    src ^= 1;
    for (int it = 1; it < NITERS; ++it) {
        k_iter<false><<<gr, bs>>>(src, nm1);
        src ^= 1;
    }

    k_final<<<dim3((n + 127) / 128, n), 128>>>(src, nm1, (const float4*)log_phi_edge, out);
    k_node<<<dim3((n + 127) / 128, n), 128>>>(out, n);
    k_write_F<<<1, 32>>>(out);
}

// round 4
// speedup vs baseline: 1.2051x; 1.2051x over previous
#include <cuda_runtime.h>
#include <math.h>

#define MAXNM1 511
#define MAXSP  (MAXNM1 + 2)
#define MAXSP2 (MAXSP * MAXSP)
#define MAXP   (MAXNM1 * MAXNM1)
#define MAXE   (2 * (MAXNM1 + 1) * MAXNM1)

// Messages as padded SoA planes: g_M[buf][slot][(pi+1)*sp + (pj+1)], pads = 1.0f
__device__ float4 g_M[2][4][MAXSP2];
__device__ float4 g_phiP[4][MAXP];
__device__ float4 g_phiE[MAXE];
__device__ double g_F;

// ---------------------------------------------------------------------------
__device__ __forceinline__ float fast_logf(float x) {
    int ix = __float_as_int(x);
    int ex = (ix >> 23) - 127;
    float m = __int_as_float((ix & 0x007FFFFF) | 0x3F800000);
    if (m > 1.41421356f) { m *= 0.5f; ex += 1; }
    float f = m - 1.0f;
    float z = f * f;
    float p = 7.0376836292e-2f;
    p = fmaf(p, f, -1.1514610310e-1f);
    p = fmaf(p, f,  1.1676998740e-1f);
    p = fmaf(p, f, -1.2420140846e-1f);
    p = fmaf(p, f,  1.4249322787e-1f);
    p = fmaf(p, f, -1.6668057665e-1f);
    p = fmaf(p, f,  2.0000714765e-1f);
    p = fmaf(p, f, -2.4999993993e-1f);
    p = fmaf(p, f,  3.3333331174e-1f);
    p = p * z * f;
    p = fmaf(-0.5f, z, p);
    return fmaf((float)ex, 0.693147180559945f, f + p);
}

__device__ __forceinline__ float pow2_inv_scale(float Z) {
    int eb = (__float_as_int(Z) >> 23) & 0xFF;
    return __int_as_float((254 - eb) << 23);
}

__device__ __forceinline__ void block_add_F(float v) {
    #pragma unroll
    for (int o = 16; o; o >>= 1) v += __shfl_down_sync(0xffffffffu, v, o);
    __shared__ float sh[32];
    int lane = threadIdx.x & 31, w = threadIdx.x >> 5;
    if (lane == 0) sh[w] = v;
    __syncthreads();
    if (w == 0) {
        int nw = (blockDim.x + 31) >> 5;
        float s = (lane < nw) ? sh[lane] : 0.0f;
        #pragma unroll
        for (int o = 16; o; o >>= 1) s += __shfl_down_sync(0xffffffffu, s, o);
        if (lane == 0) atomicAdd(&g_F, (double)s);
    }
}

__device__ __forceinline__ float4 exp4(float4 v) {
    return make_float4(__expf(v.x), __expf(v.y), __expf(v.z), __expf(v.w));
}

__device__ __forceinline__ float4 mul4(float4 a, float4 b) {
    return make_float4(a.x * b.x, a.y * b.y, a.z * b.z, a.w * b.w);
}

// ---------------------------------------------------------------------------
__global__ void k_setup(const float4* __restrict__ lpp,
                        const float4* __restrict__ lpe,
                        int P, int E, int sp) {
    int i = blockIdx.x * blockDim.x + threadIdx.x;
    int y = blockIdx.y;
    if (y < 4) {
        if (i < P) g_phiP[y][i] = exp4(__ldg(&lpp[i * 4 + y]));
    } else {
        if (i == 0) g_F = 0.0;
        if (i < E) g_phiE[i] = exp4(__ldg(&lpe[i]));
        if (i < sp) {
            float4 one = make_float4(1.f, 1.f, 1.f, 1.f);
            #pragma unroll
            for (int pl = 0; pl < 8; pl++) {
                float4* Mp = g_M[pl >> 2][pl & 3];
                Mp[i] = one;
                Mp[(sp - 1) * sp + i] = one;
                Mp[i * sp] = one;
                Mp[i * sp + (sp - 1)] = one;
            }
        }
    }
}

// ---------------------------------------------------------------------------
__device__ __forceinline__ void load_phi(int p, float Phi[16]) {
    float4 q;
    q = __ldg(&g_phiP[0][p]); Phi[0]  = q.x; Phi[1]  = q.y; Phi[2]  = q.z; Phi[3]  = q.w;
    q = __ldg(&g_phiP[1][p]); Phi[4]  = q.x; Phi[5]  = q.y; Phi[6]  = q.z; Phi[7]  = q.w;
    q = __ldg(&g_phiP[2][p]); Phi[8]  = q.x; Phi[9]  = q.y; Phi[10] = q.z; Phi[11] = q.w;
    q = __ldg(&g_phiP[3][p]); Phi[12] = q.x; Phi[13] = q.y; Phi[14] = q.z; Phi[15] = q.w;
}

// Core 16-state update: given cavity N0..N3 (as float4) and Phi, produce
// normalized output messages and store at plane offset q.
__device__ __forceinline__ void plaq_update(
    float4 N0, float4 N1, float4 N2, float4 N3, const float Phi[16],
    int dst, int q)
{
    float n0[4] = {N0.x, N0.y, N0.z, N0.w};
    float n1[4] = {N1.x, N1.y, N1.z, N1.w};
    float n2[4] = {N2.x, N2.y, N2.z, N2.w};
    float n3[4] = {N3.x, N3.y, N3.z, N3.w};
    float u0[4] = {0, 0, 0, 0}, u1[4] = {0, 0, 0, 0};
    float u2[4] = {0, 0, 0, 0}, u3[4] = {0, 0, 0, 0};
    #pragma unroll
    for (int a = 0; a < 2; a++)
    #pragma unroll
    for (int b = 0; b < 2; b++)
    #pragma unroll
    for (int c = 0; c < 2; c++)
    #pragma unroll
    for (int d = 0; d < 2; d++) {
        int idx = a * 8 + b * 4 + c * 2 + d;
        float ph = Phi[idx];
        float va = n0[a * 2 + b], vb = n1[c * 2 + d];
        float vc = n2[a * 2 + c], vd = n3[b * 2 + d];
        float q1 = ph * vc * vd;
        u0[a * 2 + b] = fmaf(q1, vb, u0[a * 2 + b]);
        u1[c * 2 + d] = fmaf(q1, va, u1[c * 2 + d]);
        float q2 = ph * va * vb;
        u2[a * 2 + c] = fmaf(q2, vd, u2[a * 2 + c]);
        u3[b * 2 + d] = fmaf(q2, vc, u3[b * 2 + d]);
    }
    {
        float Z = (u0[0] + u0[1]) + (u0[2] + u0[3]); float s = pow2_inv_scale(Z);
        g_M[dst][0][q] = make_float4(u0[0] * s, u0[1] * s, u0[2] * s, u0[3] * s);
    }
    {
        float Z = (u1[0] + u1[1]) + (u1[2] + u1[3]); float s = pow2_inv_scale(Z);
        g_M[dst][1][q] = make_float4(u1[0] * s, u1[1] * s, u1[2] * s, u1[3] * s);
    }
    {
        float Z = (u2[0] + u2[1]) + (u2[2] + u2[3]); float s = pow2_inv_scale(Z);
        g_M[dst][2][q] = make_float4(u2[0] * s, u2[1] * s, u2[2] * s, u2[3] * s);
    }
    {
        float Z = (u3[0] + u3[1]) + (u3[2] + u3[3]); float s = pow2_inv_scale(Z);
        g_M[dst][3][q] = make_float4(u3[0] * s, u3[1] * s, u3[2] * s, u3[3] * s);
    }
}

// ---------------------------------------------------------------------------
// ILP-2 iteration: thread handles plaquettes (i0, pj) and (i0+1, pj).
template<bool FIRST>
__global__ void __launch_bounds__(128) k_iter2(int src, int nm1) {
    int pj = blockIdx.x * blockDim.x + threadIdx.x;
    int i0 = blockIdx.y * 2;
    if (pj >= nm1) return;
    int n = nm1 + 1, sp = nm1 + 2, nH = n * nm1;
    bool vB = (i0 + 1) < nm1;
    int iB = vB ? (i0 + 1) : i0;

    int pA = i0 * nm1 + pj;
    int pB = iB * nm1 + pj;
    int qA = (i0 + 1) * sp + (pj + 1);
    int qB = (iB + 1) * sp + (pj + 1);
    int e2A = nH + i0 * n + pj;
    int e2B = nH + iB * n + pj;

    // phiE loads (shared: pA+nm1 == pB when vB)
    float4 hA0 = __ldg(&g_phiE[pA]);
    float4 hAB = __ldg(&g_phiE[pA + nm1]);     // A bottom == B top when vB
    float4 hB1 = __ldg(&g_phiE[pB + nm1]);
    float4 vA0 = __ldg(&g_phiE[e2A]);
    float4 vA1 = __ldg(&g_phiE[e2A + 1]);
    float4 vB0 = __ldg(&g_phiE[e2B]);
    float4 vB1 = __ldg(&g_phiE[e2B + 1]);

    float4 NA0 = hA0, NA1 = hAB, NA2 = vA0, NA3 = vA1;
    float4 NB0 = hAB, NB1 = hB1, NB2 = vB0, NB3 = vB1;
    if (!FIRST) {
        const float4* __restrict__ in0 = g_M[src][0];
        const float4* __restrict__ in1 = g_M[src][1];
        const float4* __restrict__ in2 = g_M[src][2];
        const float4* __restrict__ in3 = g_M[src][3];
        float4 rA0 = __ldg(&in1[qA - sp]);
        float4 rA1 = __ldg(&in0[qA + sp]);
        float4 rA2 = __ldg(&in3[qA - 1]);
        float4 rA3 = __ldg(&in2[qA + 1]);
        float4 rB0 = __ldg(&in1[qB - sp]);
        float4 rB1 = __ldg(&in0[qB + sp]);
        float4 rB2 = __ldg(&in3[qB - 1]);
        float4 rB3 = __ldg(&in2[qB + 1]);
        NA0 = mul4(NA0, rA0); NA1 = mul4(NA1, rA1);
        NA2 = mul4(NA2, rA2); NA3 = mul4(NA3, rA3);
        NB0 = mul4(NB0, rB0); NB1 = mul4(NB1, rB1);
        NB2 = mul4(NB2, rB2); NB3 = mul4(NB3, rB3);
    }

    int dst = src ^ 1;
    {
        float PhiA[16];
        load_phi(pA, PhiA);
        plaq_update(NA0, NA1, NA2, NA3, PhiA, dst, qA);
    }
    if (vB) {
        float PhiB[16];
        load_phi(pB, PhiB);
        plaq_update(NB0, NB1, NB2, NB3, PhiB, dst, qB);
    }
}

// ---------------------------------------------------------------------------
// Fused finals: per (i,j) in [0,n)^2: h-edge, v-edge, plaquette F term.
__global__ void k_final(int src, int nm1, const float4* __restrict__ lpe,
                        float* __restrict__ out) {
    int j = blockIdx.x * blockDim.x + threadIdx.x;
    int i = blockIdx.y;
    int n = nm1 + 1, sp = nm1 + 2, nH = n * nm1;
    float fterm = 0.0f;
    if (j < n) {
        int q = (i + 1) * sp + (j + 1);
        float4 m_h0 = __ldg(&g_M[src][0][q]);
        float4 m_h1 = __ldg(&g_M[src][1][q - sp]);
        float4 m_v0 = __ldg(&g_M[src][2][q]);
        float4 m_v1 = __ldg(&g_M[src][3][q - 1]);
        int outB = 1 + 2 * n * n;

        if (j < nm1) {
            int e = i * nm1 + j;
            float4 pe = __ldg(&g_phiE[e]);
            float tx = pe.x * m_h0.x * m_h1.x, ty = pe.y * m_h0.y * m_h1.y;
            float tz = pe.z * m_h0.z * m_h1.z, tw = pe.w * m_h0.w * m_h1.w;
            float Z = (tx + ty) + (tz + tw);
            float inv = __fdividef(1.0f, Z);
            float bx = tx * inv, by = ty * inv, bz = tz * inv, bw = tw * inv;
            int base = outB + e * 4;
            out[base + 0] = bx; out[base + 1] = by; out[base + 2] = bz; out[base + 3] = bw;
            if (i > 0 && i < nm1) {
                float4 lp = __ldg(&lpe[e]);
                fterm -= bx * (fast_logf(tx) - lp.x) + by * (fast_logf(ty) - lp.y)
                       + bz * (fast_logf(tz) - lp.z) + bw * (fast_logf(tw) - lp.w)
                       - fast_logf(Z);
            }
        }
        if (i < nm1) {
            int e = nH + i * n + j;
            float4 pe = __ldg(&g_phiE[e]);
            float tx = pe.x * m_v0.x * m_v1.x, ty = pe.y * m_v0.y * m_v1.y;
            float tz = pe.z * m_v0.z * m_v1.z, tw = pe.w * m_v0.w * m_v1.w;
            float Z = (tx + ty) + (tz + tw);
            float inv = __fdividef(1.0f, Z);
            float bx = tx * inv, by = ty * inv, bz = tz * inv, bw = tw * inv;
            int base = outB + e * 4;
            out[base + 0] = bx; out[base + 1] = by; out[base + 2] = bz; out[base + 3] = bw;
            if (j > 0 && j < nm1) {
                float4 lp = __ldg(&lpe[e]);
                fterm -= bx * (fast_logf(tx) - lp.x) + by * (fast_logf(ty) - lp.y)
                       + bz * (fast_logf(tz) - lp.z) + bw * (fast_logf(tw) - lp.w)
                       - fast_logf(Z);
            }
        }
        if (i < nm1 && j < nm1) {
            int p = i * nm1 + j;
            float4 N0 = mul4(__ldg(&g_phiE[p]),       m_h1);
            float4 N1 = mul4(__ldg(&g_phiE[p + nm1]), __ldg(&g_M[src][0][q + sp]));
            int e2 = nH + i * n + j;
            float4 N2 = mul4(__ldg(&g_phiE[e2]),      m_v1);
            float4 N3 = mul4(__ldg(&g_phiE[e2 + 1]),  __ldg(&g_M[src][2][q + 1]));
            float n0[4] = {N0.x, N0.y, N0.z, N0.w};
            float n1[4] = {N1.x, N1.y, N1.z, N1.w};
            float n2[4] = {N2.x, N2.y, N2.z, N2.w};
            float n3[4] = {N3.x, N3.y, N3.z, N3.w};
            float Phi[16];
            load_phi(p, Phi);

            float t0[4] = {0, 0, 0, 0}, t1[4] = {0, 0, 0, 0};
            float t2[4] = {0, 0, 0, 0}, t3[4] = {0, 0, 0, 0};
            #pragma unroll
            for (int a = 0; a < 2; a++)
            #pragma unroll
            for (int b = 0; b < 2; b++)
            #pragma unroll
            for (int c = 0; c < 2; c++)
            #pragma unroll
            for (int d = 0; d < 2; d++) {
                int idx = a * 8 + b * 4 + c * 2 + d;
                float ev = Phi[idx] * n0[a * 2 + b] * n1[c * 2 + d]
                                    * n2[a * 2 + c] * n3[b * 2 + d];
                t0[a * 2 + b] += ev; t1[c * 2 + d] += ev;
                t2[a * 2 + c] += ev; t3[b * 2 + d] += ev;
            }
            float sumE = (t0[0] + t0[1]) + (t0[2] + t0[3]);
            float acc = 0.0f;
            #pragma unroll
            for (int x = 0; x < 4; x++) {
                acc = fmaf(t0[x], fast_logf(n0[x]), acc);
                acc = fmaf(t1[x], fast_logf(n1[x]), acc);
                acc = fmaf(t2[x], fast_logf(n2[x]), acc);
                acc = fmaf(t3[x], fast_logf(n3[x]), acc);
            }
            fterm += __fdividef(acc, sumE) - fast_logf(sumE);
        }
    }
    block_add_F(fterm);
}

// ---------------------------------------------------------------------------
__global__ void k_node(float* __restrict__ out, int n) {
    int j = blockIdx.x * blockDim.x + threadIdx.x;
    int i = blockIdx.y;
    if (j >= n) return;
    int nm1 = n - 1, nH = n * nm1;
    const float* B = out + 1 + 2 * n * n;
    float s0 = 0.f, s1 = 0.f; int deg = 0;
    if (j < nm1) { const float* b = B + (i * nm1 + j) * 4;          s0 += b[0] + b[1]; s1 += b[2] + b[3]; deg++; }
    if (j > 0)   { const float* b = B + (i * nm1 + j - 1) * 4;      s0 += b[0] + b[2]; s1 += b[1] + b[3]; deg++; }
    if (i < nm1) { const float* b = B + (nH + i * n + j) * 4;       s0 += b[0] + b[1]; s1 += b[2] + b[3]; deg++; }
    if (i > 0)   { const float* b = B + (nH + (i - 1) * n + j) * 4; s0 += b[0] + b[2]; s1 += b[1] + b[3]; deg++; }
    float invd = __fdividef(1.0f, (float)deg);
    int v = i * n + j;
    out[1 + v * 2 + 0] = s0 * invd;
    out[1 + v * 2 + 1] = s1 * invd;
}

__global__ void k_write_F(float* __restrict__ out) {
    if (threadIdx.x == 0 && blockIdx.x == 0) out[0] = (float)(-g_F);
}

// ---------------------------------------------------------------------------
extern "C" void kernel_launch(void* const* d_in, const int* in_sizes, int n_in,
                              void* d_out, int out_size) {
    const float* log_phi_plaq = (const float*)d_in[0];
    const float* log_phi_edge = (const float*)d_in[1];

    int P = in_sizes[0] / 16;
    int E = in_sizes[1] / 4;
    int nm1 = (int)lrint(sqrt((double)P));
    int n = nm1 + 1;
    int sp = nm1 + 2;
    (void)n_in; (void)out_size;
    float* out = (float*)d_out;

    const int NITERS = 5;

    k_setup<<<dim3((E + 255) / 256, 5), 256>>>(
        (const float4*)log_phi_plaq, (const float4*)log_phi_edge, P, E, sp);

    dim3 bs(128);
    dim3 gr((nm1 + 127) / 128, (nm1 + 1) / 2);
    int src = 0;
    k_iter2<true><<<gr, bs>>>(src, nm1);
    src ^= 1;
    for (int it = 1; it < NITERS; ++it) {
        k_iter2<false><<<gr, bs>>>(src, nm1);
        src ^= 1;
    }

    k_final<<<dim3((n + 127) / 128, n), 128>>>(src, nm1, (const float4*)log_phi_edge, out);
    k_node<<<dim3((n + 127) / 128, n), 128>>>(out, n);
    k_write_F<<<1, 32>>>(out);
}

// round 5
// speedup vs baseline: 1.4990x; 1.2439x over previous
#include <cuda_runtime.h>
#include <cuda_fp16.h>
#include <math.h>

#define MAXNM1 511
#define MAXSP  (MAXNM1 + 2)
#define MAXSP2 (MAXSP * MAXSP)
#define MAXP   (MAXNM1 * MAXNM1)
#define MAXE   (2 * (MAXNM1 + 1) * MAXNM1)

// fp16 storage, fp32 compute.
// Messages: padded SoA planes, g_Mh[buf][slot][(pi+1)*sp+(pj+1)], 4 halves per msg.
__device__ uint2 g_Mh[2][4][MAXSP2];
__device__ uint4 g_phiPh[2][MAXP];   // entry k holds plaq states 8k..8k+7 as halves
__device__ uint2 g_phiEh[MAXE];      // exp(log_phi_edge) as 4 halves
__device__ double g_F;

// ---------------------------------------------------------------------------
__device__ __forceinline__ float4 h4_to_f4(uint2 v) {
    union { unsigned u; __half2 h; } a, b;
    a.u = v.x; b.u = v.y;
    float2 fa = __half22float2(a.h), fb = __half22float2(b.h);
    return make_float4(fa.x, fa.y, fb.x, fb.y);
}
__device__ __forceinline__ uint2 f4_to_h4(float4 f) {
    union { unsigned u; __half2 h; } a, b;
    a.h = __floats2half2_rn(f.x, f.y);
    b.h = __floats2half2_rn(f.z, f.w);
    return make_uint2(a.u, b.u);
}

__device__ __forceinline__ float fast_logf(float x) {
    int ix = __float_as_int(x);
    int ex = (ix >> 23) - 127;
    float m = __int_as_float((ix & 0x007FFFFF) | 0x3F800000);
    if (m > 1.41421356f) { m *= 0.5f; ex += 1; }
    float f = m - 1.0f;
    float z = f * f;
    float p = 7.0376836292e-2f;
    p = fmaf(p, f, -1.1514610310e-1f);
    p = fmaf(p, f,  1.1676998740e-1f);
    p = fmaf(p, f, -1.2420140846e-1f);
    p = fmaf(p, f,  1.4249322787e-1f);
    p = fmaf(p, f, -1.6668057665e-1f);
    p = fmaf(p, f,  2.0000714765e-1f);
    p = fmaf(p, f, -2.4999993993e-1f);
    p = fmaf(p, f,  3.3333331174e-1f);
    p = p * z * f;
    p = fmaf(-0.5f, z, p);
    return fmaf((float)ex, 0.693147180559945f, f + p);
}

__device__ __forceinline__ float pow2_inv_scale(float Z) {
    int eb = (__float_as_int(Z) >> 23) & 0xFF;
    return __int_as_float((254 - eb) << 23);
}

__device__ __forceinline__ void block_add_F(float v) {
    #pragma unroll
    for (int o = 16; o; o >>= 1) v += __shfl_down_sync(0xffffffffu, v, o);
    __shared__ float sh[32];
    int lane = threadIdx.x & 31, w = threadIdx.x >> 5;
    if (lane == 0) sh[w] = v;
    __syncthreads();
    if (w == 0) {
        int nw = (blockDim.x + 31) >> 5;
        float s = (lane < nw) ? sh[lane] : 0.0f;
        #pragma unroll
        for (int o = 16; o; o >>= 1) s += __shfl_down_sync(0xffffffffu, s, o);
        if (lane == 0) atomicAdd(&g_F, (double)s);
    }
}

__device__ __forceinline__ float4 exp4(float4 v) {
    return make_float4(__expf(v.x), __expf(v.y), __expf(v.z), __expf(v.w));
}
__device__ __forceinline__ float4 mul4(float4 a, float4 b) {
    return make_float4(a.x * b.x, a.y * b.y, a.z * b.z, a.w * b.w);
}

// ---------------------------------------------------------------------------
// Setup: y<2 -> phiP half-plane y; y==2 -> phiE + message pads + F=0
__global__ void k_setup(const float4* __restrict__ lpp,
                        const float4* __restrict__ lpe,
                        int P, int E, int sp) {
    int i = blockIdx.x * blockDim.x + threadIdx.x;
    int y = blockIdx.y;
    if (y < 2) {
        if (i < P) {
            uint2 a = f4_to_h4(exp4(__ldg(&lpp[i * 4 + 2 * y])));
            uint2 b = f4_to_h4(exp4(__ldg(&lpp[i * 4 + 2 * y + 1])));
            g_phiPh[y][i] = make_uint4(a.x, a.y, b.x, b.y);
        }
    } else {
        if (i == 0) g_F = 0.0;
        if (i < E) g_phiEh[i] = f4_to_h4(exp4(__ldg(&lpe[i])));
        if (i < sp) {
            uint2 one = f4_to_h4(make_float4(1.f, 1.f, 1.f, 1.f));
            #pragma unroll
            for (int pl = 0; pl < 8; pl++) {
                uint2* Mp = g_Mh[pl >> 2][pl & 3];
                Mp[i] = one;
                Mp[(sp - 1) * sp + i] = one;
                Mp[i * sp] = one;
                Mp[i * sp + (sp - 1)] = one;
            }
        }
    }
}

// ---------------------------------------------------------------------------
__device__ __forceinline__ void load_phi(int p, float Phi[16]) {
    uint4 q0 = __ldg(&g_phiPh[0][p]);
    uint4 q1 = __ldg(&g_phiPh[1][p]);
    float4 a = h4_to_f4(make_uint2(q0.x, q0.y));
    float4 b = h4_to_f4(make_uint2(q0.z, q0.w));
    float4 c = h4_to_f4(make_uint2(q1.x, q1.y));
    float4 d = h4_to_f4(make_uint2(q1.z, q1.w));
    Phi[0]  = a.x; Phi[1]  = a.y; Phi[2]  = a.z; Phi[3]  = a.w;
    Phi[4]  = b.x; Phi[5]  = b.y; Phi[6]  = b.z; Phi[7]  = b.w;
    Phi[8]  = c.x; Phi[9]  = c.y; Phi[10] = c.z; Phi[11] = c.w;
    Phi[12] = d.x; Phi[13] = d.y; Phi[14] = d.z; Phi[15] = d.w;
}

// Core 16-state update: cavity N0..N3 + Phi -> normalized messages at offset q.
__device__ __forceinline__ void plaq_update(
    float4 N0, float4 N1, float4 N2, float4 N3, const float Phi[16],
    int dst, int q)
{
    float n0[4] = {N0.x, N0.y, N0.z, N0.w};
    float n1[4] = {N1.x, N1.y, N1.z, N1.w};
    float n2[4] = {N2.x, N2.y, N2.z, N2.w};
    float n3[4] = {N3.x, N3.y, N3.z, N3.w};
    float u0[4] = {0, 0, 0, 0}, u1[4] = {0, 0, 0, 0};
    float u2[4] = {0, 0, 0, 0}, u3[4] = {0, 0, 0, 0};
    #pragma unroll
    for (int a = 0; a < 2; a++)
    #pragma unroll
    for (int b = 0; b < 2; b++)
    #pragma unroll
    for (int c = 0; c < 2; c++)
    #pragma unroll
    for (int d = 0; d < 2; d++) {
        int idx = a * 8 + b * 4 + c * 2 + d;
        float ph = Phi[idx];
        float va = n0[a * 2 + b], vb = n1[c * 2 + d];
        float vc = n2[a * 2 + c], vd = n3[b * 2 + d];
        float q1 = ph * vc * vd;
        u0[a * 2 + b] = fmaf(q1, vb, u0[a * 2 + b]);
        u1[c * 2 + d] = fmaf(q1, va, u1[c * 2 + d]);
        float q2 = ph * va * vb;
        u2[a * 2 + c] = fmaf(q2, vd, u2[a * 2 + c]);
        u3[b * 2 + d] = fmaf(q2, vc, u3[b * 2 + d]);
    }
    {
        float Z = (u0[0] + u0[1]) + (u0[2] + u0[3]); float s = pow2_inv_scale(Z);
        g_Mh[dst][0][q] = f4_to_h4(make_float4(u0[0] * s, u0[1] * s, u0[2] * s, u0[3] * s));
    }
    {
        float Z = (u1[0] + u1[1]) + (u1[2] + u1[3]); float s = pow2_inv_scale(Z);
        g_Mh[dst][1][q] = f4_to_h4(make_float4(u1[0] * s, u1[1] * s, u1[2] * s, u1[3] * s));
    }
    {
        float Z = (u2[0] + u2[1]) + (u2[2] + u2[3]); float s = pow2_inv_scale(Z);
        g_Mh[dst][2][q] = f4_to_h4(make_float4(u2[0] * s, u2[1] * s, u2[2] * s, u2[3] * s));
    }
    {
        float Z = (u3[0] + u3[1]) + (u3[2] + u3[3]); float s = pow2_inv_scale(Z);
        g_Mh[dst][3][q] = f4_to_h4(make_float4(u3[0] * s, u3[1] * s, u3[2] * s, u3[3] * s));
    }
}

// ---------------------------------------------------------------------------
// ILP-2 iteration: thread handles plaquettes (i0, pj) and (i0+1, pj).
template<bool FIRST>
__global__ void __launch_bounds__(128) k_iter2(int src, int nm1) {
    int pj = blockIdx.x * blockDim.x + threadIdx.x;
    int i0 = blockIdx.y * 2;
    if (pj >= nm1) return;
    int n = nm1 + 1, sp = nm1 + 2, nH = n * nm1;
    bool vB = (i0 + 1) < nm1;
    int iB = vB ? (i0 + 1) : i0;

    int pA = i0 * nm1 + pj;
    int pB = iB * nm1 + pj;
    int qA = (i0 + 1) * sp + (pj + 1);
    int qB = (iB + 1) * sp + (pj + 1);
    int e2A = nH + i0 * n + pj;
    int e2B = nH + iB * n + pj;

    float4 hA0 = h4_to_f4(__ldg(&g_phiEh[pA]));
    float4 hAB = h4_to_f4(__ldg(&g_phiEh[pA + nm1]));   // A bottom == B top when vB
    float4 hB1 = h4_to_f4(__ldg(&g_phiEh[pB + nm1]));
    float4 vA0 = h4_to_f4(__ldg(&g_phiEh[e2A]));
    float4 vA1 = h4_to_f4(__ldg(&g_phiEh[e2A + 1]));
    float4 vB0 = h4_to_f4(__ldg(&g_phiEh[e2B]));
    float4 vB1 = h4_to_f4(__ldg(&g_phiEh[e2B + 1]));

    float4 NA0 = hA0, NA1 = hAB, NA2 = vA0, NA3 = vA1;
    float4 NB0 = hAB, NB1 = hB1, NB2 = vB0, NB3 = vB1;
    if (!FIRST) {
        const uint2* __restrict__ in0 = g_Mh[src][0];
        const uint2* __restrict__ in1 = g_Mh[src][1];
        const uint2* __restrict__ in2 = g_Mh[src][2];
        const uint2* __restrict__ in3 = g_Mh[src][3];
        float4 rA0 = h4_to_f4(__ldg(&in1[qA - sp]));
        float4 rA1 = h4_to_f4(__ldg(&in0[qA + sp]));
        float4 rA2 = h4_to_f4(__ldg(&in3[qA - 1]));
        float4 rA3 = h4_to_f4(__ldg(&in2[qA + 1]));
        float4 rB0 = h4_to_f4(__ldg(&in1[qB - sp]));
        float4 rB1 = h4_to_f4(__ldg(&in0[qB + sp]));
        float4 rB2 = h4_to_f4(__ldg(&in3[qB - 1]));
        float4 rB3 = h4_to_f4(__ldg(&in2[qB + 1]));
        NA0 = mul4(NA0, rA0); NA1 = mul4(NA1, rA1);
        NA2 = mul4(NA2, rA2); NA3 = mul4(NA3, rA3);
        NB0 = mul4(NB0, rB0); NB1 = mul4(NB1, rB1);
        NB2 = mul4(NB2, rB2); NB3 = mul4(NB3, rB3);
    }

    int dst = src ^ 1;
    {
        float PhiA[16];
        load_phi(pA, PhiA);
        plaq_update(NA0, NA1, NA2, NA3, PhiA, dst, qA);
    }
    if (vB) {
        float PhiB[16];
        load_phi(pB, PhiB);
        plaq_update(NB0, NB1, NB2, NB3, PhiB, dst, qB);
    }
}

// ---------------------------------------------------------------------------
// Fused finals: per (i,j): h-edge belief, v-edge belief, plaquette F term.
// Edge phi recomputed in fp32 via __expf(lpe) so output beliefs avoid the
// fp16 phi quantization.
__global__ void k_final(int src, int nm1, const float4* __restrict__ lpe,
                        float* __restrict__ out) {
    int j = blockIdx.x * blockDim.x + threadIdx.x;
    int i = blockIdx.y;
    int n = nm1 + 1, sp = nm1 + 2, nH = n * nm1;
    float fterm = 0.0f;
    if (j < n) {
        int q = (i + 1) * sp + (j + 1);
        float4 m_h0 = h4_to_f4(__ldg(&g_Mh[src][0][q]));
        float4 m_h1 = h4_to_f4(__ldg(&g_Mh[src][1][q - sp]));
        float4 m_v0 = h4_to_f4(__ldg(&g_Mh[src][2][q]));
        float4 m_v1 = h4_to_f4(__ldg(&g_Mh[src][3][q - 1]));
        int outB = 1 + 2 * n * n;

        if (j < nm1) {
            int e = i * nm1 + j;
            float4 lp = __ldg(&lpe[e]);
            float4 pe = exp4(lp);
            float tx = pe.x * m_h0.x * m_h1.x, ty = pe.y * m_h0.y * m_h1.y;
            float tz = pe.z * m_h0.z * m_h1.z, tw = pe.w * m_h0.w * m_h1.w;
            float Z = (tx + ty) + (tz + tw);
            float inv = __fdividef(1.0f, Z);
            float bx = tx * inv, by = ty * inv, bz = tz * inv, bw = tw * inv;
            int base = outB + e * 4;
            out[base + 0] = bx; out[base + 1] = by; out[base + 2] = bz; out[base + 3] = bw;
            if (i > 0 && i < nm1) {
                fterm -= bx * (fast_logf(tx) - lp.x) + by * (fast_logf(ty) - lp.y)
                       + bz * (fast_logf(tz) - lp.z) + bw * (fast_logf(tw) - lp.w)
                       - fast_logf(Z);
            }
        }
        if (i < nm1) {
            int e = nH + i * n + j;
            float4 lp = __ldg(&lpe[e]);
            float4 pe = exp4(lp);
            float tx = pe.x * m_v0.x * m_v1.x, ty = pe.y * m_v0.y * m_v1.y;
            float tz = pe.z * m_v0.z * m_v1.z, tw = pe.w * m_v0.w * m_v1.w;
            float Z = (tx + ty) + (tz + tw);
            float inv = __fdividef(1.0f, Z);
            float bx = tx * inv, by = ty * inv, bz = tz * inv, bw = tw * inv;
            int base = outB + e * 4;
            out[base + 0] = bx; out[base + 1] = by; out[base + 2] = bz; out[base + 3] = bw;
            if (j > 0 && j < nm1) {
                fterm -= bx * (fast_logf(tx) - lp.x) + by * (fast_logf(ty) - lp.y)
                       + bz * (fast_logf(tz) - lp.z) + bw * (fast_logf(tw) - lp.w)
                       - fast_logf(Z);
            }
        }
        if (i < nm1 && j < nm1) {
            int p = i * nm1 + j;
            float4 N0 = mul4(h4_to_f4(__ldg(&g_phiEh[p])),       m_h1);
            float4 N1 = mul4(h4_to_f4(__ldg(&g_phiEh[p + nm1])),
                             h4_to_f4(__ldg(&g_Mh[src][0][q + sp])));
            int e2 = nH + i * n + j;
            float4 N2 = mul4(h4_to_f4(__ldg(&g_phiEh[e2])),      m_v1);
            float4 N3 = mul4(h4_to_f4(__ldg(&g_phiEh[e2 + 1])),
                             h4_to_f4(__ldg(&g_Mh[src][2][q + 1])));
            float n0[4] = {N0.x, N0.y, N0.z, N0.w};
            float n1[4] = {N1.x, N1.y, N1.z, N1.w};
            float n2[4] = {N2.x, N2.y, N2.z, N2.w};
            float n3[4] = {N3.x, N3.y, N3.z, N3.w};
            float Phi[16];
            load_phi(p, Phi);

            float t0[4] = {0, 0, 0, 0}, t1[4] = {0, 0, 0, 0};
            float t2[4] = {0, 0, 0, 0}, t3[4] = {0, 0, 0, 0};
            #pragma unroll
            for (int a = 0; a < 2; a++)
            #pragma unroll
            for (int b = 0; b < 2; b++)
            #pragma unroll
            for (int c = 0; c < 2; c++)
            #pragma unroll
            for (int d = 0; d < 2; d++) {
                int idx = a * 8 + b * 4 + c * 2 + d;
                float ev = Phi[idx] * n0[a * 2 + b] * n1[c * 2 + d]
                                    * n2[a * 2 + c] * n3[b * 2 + d];
                t0[a * 2 + b] += ev; t1[c * 2 + d] += ev;
                t2[a * 2 + c] += ev; t3[b * 2 + d] += ev;
            }
            float sumE = (t0[0] + t0[1]) + (t0[2] + t0[3]);
            float acc = 0.0f;
            #pragma unroll
            for (int x = 0; x < 4; x++) {
                acc = fmaf(t0[x], fast_logf(n0[x]), acc);
                acc = fmaf(t1[x], fast_logf(n1[x]), acc);
                acc = fmaf(t2[x], fast_logf(n2[x]), acc);
                acc = fmaf(t3[x], fast_logf(n3[x]), acc);
            }
            fterm += __fdividef(acc, sumE) - fast_logf(sumE);
        }
    }
    block_add_F(fterm);
}

// ---------------------------------------------------------------------------
__global__ void k_node(float* __restrict__ out, int n) {
    int j = blockIdx.x * blockDim.x + threadIdx.x;
    int i = blockIdx.y;
    if (j >= n) return;
    int nm1 = n - 1, nH = n * nm1;
    const float* B = out + 1 + 2 * n * n;
    float s0 = 0.f, s1 = 0.f; int deg = 0;
    if (j < nm1) { const float* b = B + (i * nm1 + j) * 4;          s0 += b[0] + b[1]; s1 += b[2] + b[3]; deg++; }
    if (j > 0)   { const float* b = B + (i * nm1 + j - 1) * 4;      s0 += b[0] + b[2]; s1 += b[1] + b[3]; deg++; }
    if (i < nm1) { const float* b = B + (nH + i * n + j) * 4;       s0 += b[0] + b[1]; s1 += b[2] + b[3]; deg++; }
    if (i > 0)   { const float* b = B + (nH + (i - 1) * n + j) * 4; s0 += b[0] + b[2]; s1 += b[1] + b[3]; deg++; }
    float invd = __fdividef(1.0f, (float)deg);
    int v = i * n + j;
    out[1 + v * 2 + 0] = s0 * invd;
    out[1 + v * 2 + 1] = s1 * invd;
}

__global__ void k_write_F(float* __restrict__ out) {
    if (threadIdx.x == 0 && blockIdx.x == 0) out[0] = (float)(-g_F);
}

// ---------------------------------------------------------------------------
extern "C" void kernel_launch(void* const* d_in, const int* in_sizes, int n_in,
                              void* d_out, int out_size) {
    const float* log_phi_plaq = (const float*)d_in[0];
    const float* log_phi_edge = (const float*)d_in[1];

    int P = in_sizes[0] / 16;
    int E = in_sizes[1] / 4;
    int nm1 = (int)lrint(sqrt((double)P));
    int n = nm1 + 1;
    int sp = nm1 + 2;
    (void)n_in; (void)out_size;
    float* out = (float*)d_out;

    const int NITERS = 5;

    k_setup<<<dim3((E + 255) / 256, 3), 256>>>(
        (const float4*)log_phi_plaq, (const float4*)log_phi_edge, P, E, sp);

    dim3 bs(128);
    dim3 gr((nm1 + 127) / 128, (nm1 + 1) / 2);
    int src = 0;
    k_iter2<true><<<gr, bs>>>(src, nm1);
    src ^= 1;
    for (int it = 1; it < NITERS; ++it) {
        k_iter2<false><<<gr, bs>>>(src, nm1);
        src ^= 1;
    }

    k_final<<<dim3((n + 127) / 128, n), 128>>>(src, nm1, (const float4*)log_phi_edge, out);
    k_node<<<dim3((n + 127) / 128, n), 128>>>(out, n);
    k_write_F<<<1, 32>>>(out);
}

// round 6
// speedup vs baseline: 1.7301x; 1.1541x over previous
#include <cuda_runtime.h>
#include <cuda_fp16.h>
#include <math.h>

#define MAXNM1 511
#define MAXSP  (MAXNM1 + 2)
#define MAXSP2 (MAXSP * MAXSP)
#define MAXP   (MAXNM1 * MAXNM1)
#define MAXE   (2 * (MAXNM1 + 1) * MAXNM1)

// fp16 storage, fp32 compute.
__device__ uint2 g_Mh[2][4][MAXSP2];  // messages: padded SoA planes, pads = 1.0h
__device__ uint4 g_phiPh[2][MAXP];    // plaq phi as halves (8 states per entry)
__device__ uint2 g_phiEh[MAXE];       // edge phi as halves
__device__ double g_F;

// ---------------------------------------------------------------------------
__device__ __forceinline__ float4 h4_to_f4(uint2 v) {
    union { unsigned u; __half2 h; } a, b;
    a.u = v.x; b.u = v.y;
    float2 fa = __half22float2(a.h), fb = __half22float2(b.h);
    return make_float4(fa.x, fa.y, fb.x, fb.y);
}
__device__ __forceinline__ uint2 f4_to_h4(float4 f) {
    union { unsigned u; __half2 h; } a, b;
    a.h = __floats2half2_rn(f.x, f.y);
    b.h = __floats2half2_rn(f.z, f.w);
    return make_uint2(a.u, b.u);
}

__device__ __forceinline__ float fast_logf(float x) {
    int ix = __float_as_int(x);
    int ex = (ix >> 23) - 127;
    float m = __int_as_float((ix & 0x007FFFFF) | 0x3F800000);
    if (m > 1.41421356f) { m *= 0.5f; ex += 1; }
    float f = m - 1.0f;
    float z = f * f;
    float p = 7.0376836292e-2f;
    p = fmaf(p, f, -1.1514610310e-1f);
    p = fmaf(p, f,  1.1676998740e-1f);
    p = fmaf(p, f, -1.2420140846e-1f);
    p = fmaf(p, f,  1.4249322787e-1f);
    p = fmaf(p, f, -1.6668057665e-1f);
    p = fmaf(p, f,  2.0000714765e-1f);
    p = fmaf(p, f, -2.4999993993e-1f);
    p = fmaf(p, f,  3.3333331174e-1f);
    p = p * z * f;
    p = fmaf(-0.5f, z, p);
    return fmaf((float)ex, 0.693147180559945f, f + p);
}

__device__ __forceinline__ float pow2_inv_scale(float Z) {
    int eb = (__float_as_int(Z) >> 23) & 0xFF;
    return __int_as_float((254 - eb) << 23);
}

__device__ __forceinline__ void block_add_F(float v) {
    #pragma unroll
    for (int o = 16; o; o >>= 1) v += __shfl_down_sync(0xffffffffu, v, o);
    __shared__ float sh[32];
    int lane = threadIdx.x & 31, w = threadIdx.x >> 5;
    if (lane == 0) sh[w] = v;
    __syncthreads();
    if (w == 0) {
        int nw = (blockDim.x + 31) >> 5;
        float s = (lane < nw) ? sh[lane] : 0.0f;
        #pragma unroll
        for (int o = 16; o; o >>= 1) s += __shfl_down_sync(0xffffffffu, s, o);
        if (lane == 0) atomicAdd(&g_F, (double)s);
    }
}

__device__ __forceinline__ float4 exp4(float4 v) {
    return make_float4(__expf(v.x), __expf(v.y), __expf(v.z), __expf(v.w));
}
__device__ __forceinline__ float4 mul4(float4 a, float4 b) {
    return make_float4(a.x * b.x, a.y * b.y, a.z * b.z, a.w * b.w);
}

// ---------------------------------------------------------------------------
__device__ __forceinline__ void load_phi(int p, float Phi[16]) {
    uint4 q0 = __ldg(&g_phiPh[0][p]);
    uint4 q1 = __ldg(&g_phiPh[1][p]);
    float4 a = h4_to_f4(make_uint2(q0.x, q0.y));
    float4 b = h4_to_f4(make_uint2(q0.z, q0.w));
    float4 c = h4_to_f4(make_uint2(q1.x, q1.y));
    float4 d = h4_to_f4(make_uint2(q1.z, q1.w));
    Phi[0]  = a.x; Phi[1]  = a.y; Phi[2]  = a.z; Phi[3]  = a.w;
    Phi[4]  = b.x; Phi[5]  = b.y; Phi[6]  = b.z; Phi[7]  = b.w;
    Phi[8]  = c.x; Phi[9]  = c.y; Phi[10] = c.z; Phi[11] = c.w;
    Phi[12] = d.x; Phi[13] = d.y; Phi[14] = d.z; Phi[15] = d.w;
}

// Core 16-state update: cavity N0..N3 + Phi -> normalized messages at offset q.
__device__ __forceinline__ void plaq_update(
    float4 N0, float4 N1, float4 N2, float4 N3, const float Phi[16],
    int dst, int q)
{
    float n0[4] = {N0.x, N0.y, N0.z, N0.w};
    float n1[4] = {N1.x, N1.y, N1.z, N1.w};
    float n2[4] = {N2.x, N2.y, N2.z, N2.w};
    float n3[4] = {N3.x, N3.y, N3.z, N3.w};
    float u0[4] = {0, 0, 0, 0}, u1[4] = {0, 0, 0, 0};
    float u2[4] = {0, 0, 0, 0}, u3[4] = {0, 0, 0, 0};
    #pragma unroll
    for (int a = 0; a < 2; a++)
    #pragma unroll
    for (int b = 0; b < 2; b++)
    #pragma unroll
    for (int c = 0; c < 2; c++)
    #pragma unroll
    for (int d = 0; d < 2; d++) {
        int idx = a * 8 + b * 4 + c * 2 + d;
        float ph = Phi[idx];
        float va = n0[a * 2 + b], vb = n1[c * 2 + d];
        float vc = n2[a * 2 + c], vd = n3[b * 2 + d];
        float q1 = ph * vc * vd;
        u0[a * 2 + b] = fmaf(q1, vb, u0[a * 2 + b]);
        u1[c * 2 + d] = fmaf(q1, va, u1[c * 2 + d]);
        float q2 = ph * va * vb;
        u2[a * 2 + c] = fmaf(q2, vd, u2[a * 2 + c]);
        u3[b * 2 + d] = fmaf(q2, vc, u3[b * 2 + d]);
    }
    {
        float Z = (u0[0] + u0[1]) + (u0[2] + u0[3]); float s = pow2_inv_scale(Z);
        g_Mh[dst][0][q] = f4_to_h4(make_float4(u0[0] * s, u0[1] * s, u0[2] * s, u0[3] * s));
    }
    {
        float Z = (u1[0] + u1[1]) + (u1[2] + u1[3]); float s = pow2_inv_scale(Z);
        g_Mh[dst][1][q] = f4_to_h4(make_float4(u1[0] * s, u1[1] * s, u1[2] * s, u1[3] * s));
    }
    {
        float Z = (u2[0] + u2[1]) + (u2[2] + u2[3]); float s = pow2_inv_scale(Z);
        g_Mh[dst][2][q] = f4_to_h4(make_float4(u2[0] * s, u2[1] * s, u2[2] * s, u2[3] * s));
    }
    {
        float Z = (u3[0] + u3[1]) + (u3[2] + u3[3]); float s = pow2_inv_scale(Z);
        g_Mh[dst][3][q] = f4_to_h4(make_float4(u3[0] * s, u3[1] * s, u3[2] * s, u3[3] * s));
    }
}

// ---------------------------------------------------------------------------
// Fused setup + iteration 1.  Reads fp32 inputs, computes exp in-register,
// performs the first BP update (uniform incoming messages -> cavity = phiE),
// and writes the fp16 phi tables used by iterations 2..5.
// Last grid.y row initializes the pad ring of all 8 message planes and g_F.
// Message output -> buffer 0.
__global__ void __launch_bounds__(128) k_first(
    const float4* __restrict__ lpp, const float4* __restrict__ lpe, int nm1)
{
    int sp = nm1 + 2;
    if (blockIdx.y == gridDim.y - 1) {
        int tot = gridDim.x * blockDim.x;
        int t = blockIdx.x * blockDim.x + threadIdx.x;
        if (t == 0) g_F = 0.0;
        uint2 one = f4_to_h4(make_float4(1.f, 1.f, 1.f, 1.f));
        for (int i = t; i < sp; i += tot) {
            #pragma unroll
            for (int pl = 0; pl < 8; pl++) {
                uint2* Mp = g_Mh[pl >> 2][pl & 3];
                Mp[i] = one;
                Mp[(sp - 1) * sp + i] = one;
                Mp[i * sp] = one;
                Mp[i * sp + (sp - 1)] = one;
            }
        }
        return;
    }

    int pj = blockIdx.x * blockDim.x + threadIdx.x;
    int i0 = blockIdx.y * 2;
    if (pj >= nm1) return;
    int n = nm1 + 1, nH = n * nm1;
    bool vB = (i0 + 1) < nm1;
    int iB = vB ? (i0 + 1) : i0;

    int pA = i0 * nm1 + pj;
    int pB = iB * nm1 + pj;
    int qA = (i0 + 1) * sp + (pj + 1);
    int qB = (iB + 1) * sp + (pj + 1);
    int e2A = nH + i0 * n + pj;
    int e2B = nH + iB * n + pj;

    // --- edge phi (fp32 exp) ---
    float4 fT  = exp4(__ldg(&lpe[pA]));          // h(i0, pj)
    float4 fM  = exp4(__ldg(&lpe[pA + nm1]));    // h(i0+1, pj)
    float4 fLA = exp4(__ldg(&lpe[e2A]));         // v(i0, pj)
    float4 fRA = exp4(__ldg(&lpe[e2A + 1]));     // v(i0, pj+1)
    float4 fB = fM, fLB = fLA, fRB = fRA;
    if (vB) {
        fB  = exp4(__ldg(&lpe[pB + nm1]));
        fLB = exp4(__ldg(&lpe[e2B]));
        fRB = exp4(__ldg(&lpe[e2B + 1]));
    }

    // ownership writes of fp16 edge phi (each edge exactly once):
    // this pair owns h(2by, j) and h(2by+1, j); each plaq owns its left v edge;
    // right column additionally owns the right border v edge.
    g_phiEh[pA] = f4_to_h4(fT);
    g_phiEh[pA + nm1] = f4_to_h4(fM);
    g_phiEh[e2A] = f4_to_h4(fLA);
    if (vB) g_phiEh[e2B] = f4_to_h4(fLB);
    if (pj == nm1 - 1) {
        g_phiEh[e2A + 1] = f4_to_h4(fRA);
        if (vB) g_phiEh[e2B + 1] = f4_to_h4(fRB);
    }

    // --- plaq A: phi + update ---
    {
        float Phi[16];
        float4 a = exp4(__ldg(&lpp[pA * 4 + 0]));
        float4 b = exp4(__ldg(&lpp[pA * 4 + 1]));
        float4 c = exp4(__ldg(&lpp[pA * 4 + 2]));
        float4 d = exp4(__ldg(&lpp[pA * 4 + 3]));
        Phi[0]=a.x; Phi[1]=a.y; Phi[2]=a.z; Phi[3]=a.w;
        Phi[4]=b.x; Phi[5]=b.y; Phi[6]=b.z; Phi[7]=b.w;
        Phi[8]=c.x; Phi[9]=c.y; Phi[10]=c.z; Phi[11]=c.w;
        Phi[12]=d.x; Phi[13]=d.y; Phi[14]=d.z; Phi[15]=d.w;
        uint2 h0 = f4_to_h4(a), h1 = f4_to_h4(b), h2 = f4_to_h4(c), h3 = f4_to_h4(d);
        g_phiPh[0][pA] = make_uint4(h0.x, h0.y, h1.x, h1.y);
        g_phiPh[1][pA] = make_uint4(h2.x, h2.y, h3.x, h3.y);
        plaq_update(fT, fM, fLA, fRA, Phi, 0, qA);
    }
    // --- plaq B ---
    if (vB) {
        float Phi[16];
        float4 a = exp4(__ldg(&lpp[pB * 4 + 0]));
        float4 b = exp4(__ldg(&lpp[pB * 4 + 1]));
        float4 c = exp4(__ldg(&lpp[pB * 4 + 2]));
        float4 d = exp4(__ldg(&lpp[pB * 4 + 3]));
        Phi[0]=a.x; Phi[1]=a.y; Phi[2]=a.z; Phi[3]=a.w;
        Phi[4]=b.x; Phi[5]=b.y; Phi[6]=b.z; Phi[7]=b.w;
        Phi[8]=c.x; Phi[9]=c.y; Phi[10]=c.z; Phi[11]=c.w;
        Phi[12]=d.x; Phi[13]=d.y; Phi[14]=d.z; Phi[15]=d.w;
        uint2 h0 = f4_to_h4(a), h1 = f4_to_h4(b), h2 = f4_to_h4(c), h3 = f4_to_h4(d);
        g_phiPh[0][pB] = make_uint4(h0.x, h0.y, h1.x, h1.y);
        g_phiPh[1][pB] = make_uint4(h2.x, h2.y, h3.x, h3.y);
        plaq_update(fM, fB, fLB, fRB, Phi, 0, qB);
    }
}

// ---------------------------------------------------------------------------
// ILP-2 iteration: thread handles plaquettes (i0, pj) and (i0+1, pj).
// SRC is a compile-time buffer index (constant-folded plane addressing).
template<int SRC>
__global__ void __launch_bounds__(128) k_iter2(int nm1) {
    int pj = blockIdx.x * blockDim.x + threadIdx.x;
    int i0 = blockIdx.y * 2;
    if (pj >= nm1) return;
    int n = nm1 + 1, sp = nm1 + 2, nH = n * nm1;
    bool vB = (i0 + 1) < nm1;
    int iB = vB ? (i0 + 1) : i0;

    int pA = i0 * nm1 + pj;
    int pB = iB * nm1 + pj;
    int qA = (i0 + 1) * sp + (pj + 1);
    int qB = (iB + 1) * sp + (pj + 1);
    int e2A = nH + i0 * n + pj;
    int e2B = nH + iB * n + pj;

    float4 hA0 = h4_to_f4(__ldg(&g_phiEh[pA]));
    float4 hAB = h4_to_f4(__ldg(&g_phiEh[pA + nm1]));
    float4 hB1 = h4_to_f4(__ldg(&g_phiEh[pB + nm1]));
    float4 vA0 = h4_to_f4(__ldg(&g_phiEh[e2A]));
    float4 vA1 = h4_to_f4(__ldg(&g_phiEh[e2A + 1]));
    float4 vB0 = h4_to_f4(__ldg(&g_phiEh[e2B]));
    float4 vB1 = h4_to_f4(__ldg(&g_phiEh[e2B + 1]));

    const uint2* __restrict__ in0 = g_Mh[SRC][0];
    const uint2* __restrict__ in1 = g_Mh[SRC][1];
    const uint2* __restrict__ in2 = g_Mh[SRC][2];
    const uint2* __restrict__ in3 = g_Mh[SRC][3];
    float4 NA0 = mul4(hA0, h4_to_f4(__ldg(&in1[qA - sp])));
    float4 NA1 = mul4(hAB, h4_to_f4(__ldg(&in0[qA + sp])));
    float4 NA2 = mul4(vA0, h4_to_f4(__ldg(&in3[qA - 1])));
    float4 NA3 = mul4(vA1, h4_to_f4(__ldg(&in2[qA + 1])));
    float4 NB0 = mul4(hAB, h4_to_f4(__ldg(&in1[qB - sp])));
    float4 NB1 = mul4(hB1, h4_to_f4(__ldg(&in0[qB + sp])));
    float4 NB2 = mul4(vB0, h4_to_f4(__ldg(&in3[qB - 1])));
    float4 NB3 = mul4(vB1, h4_to_f4(__ldg(&in2[qB + 1])));

    constexpr int DST = SRC ^ 1;
    {
        float PhiA[16];
        load_phi(pA, PhiA);
        plaq_update(NA0, NA1, NA2, NA3, PhiA, DST, qA);
    }
    if (vB) {
        float PhiB[16];
        load_phi(pB, PhiB);
        plaq_update(NB0, NB1, NB2, NB3, PhiB, DST, qB);
    }
}

// ---------------------------------------------------------------------------
// Fused finals: per (i,j): h-edge belief, v-edge belief, plaquette F term.
__global__ void k_final(int src, int nm1, const float4* __restrict__ lpe,
                        float* __restrict__ out) {
    int j = blockIdx.x * blockDim.x + threadIdx.x;
    int i = blockIdx.y;
    int n = nm1 + 1, sp = nm1 + 2, nH = n * nm1;
    float fterm = 0.0f;
    if (j < n) {
        int q = (i + 1) * sp + (j + 1);
        float4 m_h0 = h4_to_f4(__ldg(&g_Mh[src][0][q]));
        float4 m_h1 = h4_to_f4(__ldg(&g_Mh[src][1][q - sp]));
        float4 m_v0 = h4_to_f4(__ldg(&g_Mh[src][2][q]));
        float4 m_v1 = h4_to_f4(__ldg(&g_Mh[src][3][q - 1]));
        int outB = 1 + 2 * n * n;

        if (j < nm1) {
            int e = i * nm1 + j;
            float4 lp = __ldg(&lpe[e]);
            float4 pe = exp4(lp);
            float tx = pe.x * m_h0.x * m_h1.x, ty = pe.y * m_h0.y * m_h1.y;
            float tz = pe.z * m_h0.z * m_h1.z, tw = pe.w * m_h0.w * m_h1.w;
            float Z = (tx + ty) + (tz + tw);
            float inv = __fdividef(1.0f, Z);
            float bx = tx * inv, by = ty * inv, bz = tz * inv, bw = tw * inv;
            int base = outB + e * 4;
            out[base + 0] = bx; out[base + 1] = by; out[base + 2] = bz; out[base + 3] = bw;
            if (i > 0 && i < nm1) {
                fterm -= bx * (fast_logf(tx) - lp.x) + by * (fast_logf(ty) - lp.y)
                       + bz * (fast_logf(tz) - lp.z) + bw * (fast_logf(tw) - lp.w)
                       - fast_logf(Z);
            }
        }
        if (i < nm1) {
            int e = nH + i * n + j;
            float4 lp = __ldg(&lpe[e]);
            float4 pe = exp4(lp);
            float tx = pe.x * m_v0.x * m_v1.x, ty = pe.y * m_v0.y * m_v1.y;
            float tz = pe.z * m_v0.z * m_v1.z, tw = pe.w * m_v0.w * m_v1.w;
            float Z = (tx + ty) + (tz + tw);
            float inv = __fdividef(1.0f, Z);
            float bx = tx * inv, by = ty * inv, bz = tz * inv, bw = tw * inv;
            int base = outB + e * 4;
            out[base + 0] = bx; out[base + 1] = by; out[base + 2] = bz; out[base + 3] = bw;
            if (j > 0 && j < nm1) {
                fterm -= bx * (fast_logf(tx) - lp.x) + by * (fast_logf(ty) - lp.y)
                       + bz * (fast_logf(tz) - lp.z) + bw * (fast_logf(tw) - lp.w)
                       - fast_logf(Z);
            }
        }
        if (i < nm1 && j < nm1) {
            int p = i * nm1 + j;
            float4 N0 = mul4(h4_to_f4(__ldg(&g_phiEh[p])),       m_h1);
            float4 N1 = mul4(h4_to_f4(__ldg(&g_phiEh[p + nm1])),
                             h4_to_f4(__ldg(&g_Mh[src][0][q + sp])));
            int e2 = nH + i * n + j;
            float4 N2 = mul4(h4_to_f4(__ldg(&g_phiEh[e2])),      m_v1);
            float4 N3 = mul4(h4_to_f4(__ldg(&g_phiEh[e2 + 1])),
                             h4_to_f4(__ldg(&g_Mh[src][2][q + 1])));
            float n0[4] = {N0.x, N0.y, N0.z, N0.w};
            float n1[4] = {N1.x, N1.y, N1.z, N1.w};
            float n2[4] = {N2.x, N2.y, N2.z, N2.w};
            float n3[4] = {N3.x, N3.y, N3.z, N3.w};
            float Phi[16];
            load_phi(p, Phi);

            float t0[4] = {0, 0, 0, 0}, t1[4] = {0, 0, 0, 0};
            float t2[4] = {0, 0, 0, 0}, t3[4] = {0, 0, 0, 0};
            #pragma unroll
            for (int a = 0; a < 2; a++)
            #pragma unroll
            for (int b = 0; b < 2; b++)
            #pragma unroll
            for (int c = 0; c < 2; c++)
            #pragma unroll
            for (int d = 0; d < 2; d++) {
                int idx = a * 8 + b * 4 + c * 2 + d;
                float ev = Phi[idx] * n0[a * 2 + b] * n1[c * 2 + d]
                                    * n2[a * 2 + c] * n3[b * 2 + d];
                t0[a * 2 + b] += ev; t1[c * 2 + d] += ev;
                t2[a * 2 + c] += ev; t3[b * 2 + d] += ev;
            }
            float sumE = (t0[0] + t0[1]) + (t0[2] + t0[3]);
            float acc = 0.0f;
            #pragma unroll
            for (int x = 0; x < 4; x++) {
                acc = fmaf(t0[x], fast_logf(n0[x]), acc);
                acc = fmaf(t1[x], fast_logf(n1[x]), acc);
                acc = fmaf(t2[x], fast_logf(n2[x]), acc);
                acc = fmaf(t3[x], fast_logf(n3[x]), acc);
            }
            fterm += __fdividef(acc, sumE) - fast_logf(sumE);
        }
    }
    block_add_F(fterm);
}

// ---------------------------------------------------------------------------
// Unary marginals; thread (0,0) also writes -F (g_F complete after k_final).
__global__ void k_node(float* __restrict__ out, int n) {
    int j = blockIdx.x * blockDim.x + threadIdx.x;
    int i = blockIdx.y;
    if (i == 0 && j == 0) out[0] = (float)(-g_F);
    if (j >= n) return;
    int nm1 = n - 1, nH = n * nm1;
    const float* B = out + 1 + 2 * n * n;
    float s0 = 0.f, s1 = 0.f; int deg = 0;
    if (j < nm1) { const float* b = B + (i * nm1 + j) * 4;          s0 += b[0] + b[1]; s1 += b[2] + b[3]; deg++; }
    if (j > 0)   { const float* b = B + (i * nm1 + j - 1) * 4;      s0 += b[0] + b[2]; s1 += b[1] + b[3]; deg++; }
    if (i < nm1) { const float* b = B + (nH + i * n + j) * 4;       s0 += b[0] + b[1]; s1 += b[2] + b[3]; deg++; }
    if (i > 0)   { const float* b = B + (nH + (i - 1) * n + j) * 4; s0 += b[0] + b[2]; s1 += b[1] + b[3]; deg++; }
    float invd = __fdividef(1.0f, (float)deg);
    int v = i * n + j;
    out[1 + v * 2 + 0] = s0 * invd;
    out[1 + v * 2 + 1] = s1 * invd;
}

// ---------------------------------------------------------------------------
extern "C" void kernel_launch(void* const* d_in, const int* in_sizes, int n_in,
                              void* d_out, int out_size) {
    const float* log_phi_plaq = (const float*)d_in[0];
    const float* log_phi_edge = (const float*)d_in[1];

    int P = in_sizes[0] / 16;
    int E = in_sizes[1] / 4;
    int nm1 = (int)lrint(sqrt((double)P));
    int n = nm1 + 1;
    (void)E; (void)n_in; (void)out_size;
    float* out = (float*)d_out;

    dim3 bs(128);
    dim3 grF((nm1 + 127) / 128, (nm1 + 1) / 2 + 1);  // +1 row for pads
    dim3 gr((nm1 + 127) / 128, (nm1 + 1) / 2);

    // iter 1 (fused with setup) -> buf 0
    k_first<<<grF, bs>>>((const float4*)log_phi_plaq, (const float4*)log_phi_edge, nm1);
    // iters 2..5: 0->1, 1->0, 0->1, 1->0  (final state in buf 0)
    k_iter2<0><<<gr, bs>>>(nm1);
    k_iter2<1><<<gr, bs>>>(nm1);
    k_iter2<0><<<gr, bs>>>(nm1);
    k_iter2<1><<<gr, bs>>>(nm1);

    k_final<<<dim3((n + 127) / 128, n), 128>>>(0, nm1, (const float4*)log_phi_edge, out);
    k_node<<<dim3((n + 127) / 128, n), 128>>>(out, n);
}